// round 8
// baseline (speedup 1.0000x reference)
#include <cuda_runtime.h>

#define LSEQ 2048
#define NBH 128
typedef unsigned long long ull;

// -------- device scratch --------
__device__ float g_F[2][2][1024 * 64];   // [src][par][t<1024][64 grouped cols]
__device__ int   g_cmap[2][2][64];       // grouped col -> pl*4096 + m
__device__ float g_Binv2[128 * 1024];    // [kslot][t<1024] parity-grouped cos/sin
__device__ int   g_pmap[64];             // mode m -> kslot (cos; sin at +1)
__device__ float g_G[2][2][NBH][8192];   // [ks][src][bh][pl][e][m]
__device__ float g_X[2][NBH][8192];      // projected spectra
__device__ float g_Z[NBH][8192];         // attention-applied spectra [bh][pl][e][x]
__device__ float g_Y[NBH * 8192];        // irDFT coeffs, parity-grouped [bh][kslot][o]

// -------- f32x2 helpers --------
__device__ __forceinline__ ull dup2(float x) {
    ull r; asm("mov.b64 %0, {%1, %1};" : "=l"(r) : "f"(x)); return r;
}
__device__ __forceinline__ void fma2(ull& d, ull a, ull b) {
    asm("fma.rn.f32x2 %0, %1, %2, %3;" : "=l"(d) : "l"(a), "l"(b), "l"(d));
}
__device__ __forceinline__ ull add2(ull a, ull b) {
    ull r; asm("add.rn.f32x2 %0, %1, %2;" : "=l"(r) : "l"(a), "l"(b)); return r;
}
__device__ __forceinline__ float2 unpk(ull v) {
    float2 r; asm("mov.b64 {%0, %1}, %2;" : "=f"(r.x), "=f"(r.y) : "l"(v)); return r;
}
__device__ __forceinline__ ull neg2(ull v) { return v ^ 0x8000000080000000ULL; }

// ---------------- init: parity-grouped inverse basis + mode->slot map ----------------
__global__ void k_init_binv2(const int* __restrict__ idxq) {
    int idx = blockIdx.x * blockDim.x + threadIdx.x;
    if (idx >= 1024 * 64) return;
    int t = idx >> 6, m = idx & 63;
    int f = idxq[m];
    int par = f & 1;
    int rank = 0;
    for (int mm = 0; mm < m; mm++) rank += ((idxq[mm] & 1) == par);
    int slot = par * 64 + 2 * rank;
    int r = (f * t) & (LSEQ - 1);
    float sn, cs;
    sincospif((float)r * (1.0f / 1024.0f), &sn, &cs);
    g_Binv2[slot * 1024 + t]       = cs;
    g_Binv2[(slot + 1) * 1024 + t] = sn;
    if (t == 0) g_pmap[m] = slot;
}

// ---------------- init: folded forward basis (parity-grouped cols) ----------------
__global__ void k_init_f(const int* __restrict__ idx, int src) {
    int gidx = blockIdx.x * blockDim.x + threadIdx.x;
    if (gidx >= 1024 * 64) return;
    int t = gidx >> 6, m = gidx & 63;
    int f = idx[m];
    int par = f & 1;
    int s = 0;
    for (int mm = 0; mm < m; mm++) s += ((idx[mm] & 1) == par);
    int r = (f * t) & (LSEQ - 1);
    float sn, cs;
    sincospif((float)r * (1.0f / 1024.0f), &sn, &cs);
    float* F = g_F[src][par];
    F[t * 64 + 2 * s]     = cs;
    F[t * 64 + 2 * s + 1] = -sn;
    if (t == 0) {
        g_cmap[src][par][2 * s]     = m;
        g_cmap[src][par][2 * s + 1] = 4096 + m;
    }
}

// ---------------- K1: folded forward DFT GEMM, 128 thr, 8x8 thread tile ----------------
// grid 512: (par, ks, pair, src). C[128 rows(2 heads)][64 grouped cols], K=512.
__global__ void __launch_bounds__(128) k_fwd3(const float* __restrict__ q,
                                              const float* __restrict__ k) {
    int bx = blockIdx.x;
    int par  = bx & 1;
    int ks   = (bx >> 1) & 1;
    int pair = (bx >> 2) & 63;
    int src  = bx >> 8;
    int b  = pair >> 2;
    int h0 = (pair & 3) * 2;
    const float* x  = (src == 0 ? q : k) + (size_t)b * (LSEQ * 512) + h0 * 64;
    const float* Ff = g_F[src][par];
    const float sgn = par ? -1.f : 1.f;
    int tbase = ks * 512;

    __shared__ float As[2][16 * 128];
    __shared__ float Bs[2][16 * 64];

    int tid = threadIdx.x;
    int g  = tid >> 3;         // 0..15 row group
    int tx = tid & 7;          // 0..7 col group
    int r0 = g * 8;

    ull acc[8][4];
#pragma unroll
    for (int i = 0; i < 8; i++)
#pragma unroll
        for (int j = 0; j < 4; j++) acc[i][j] = 0ULL;

    float4 u[4], v[4], pF[2];
    // A loaders: 512 float4/chunk, 4/thread; B: 256 float4, 2/thread
#pragma unroll
    for (int r = 0; r < 4; r++) {
        int idx = tid + r * 128;
        int row = idx >> 5, c4 = (idx & 31) * 4;
        u[r] = *(const float4*)(x + (size_t)(tbase + row) * 512 + c4);
        v[r] = *(const float4*)(x + (size_t)(tbase + row + 1024) * 512 + c4);
    }
#pragma unroll
    for (int r = 0; r < 2; r++) {
        int idx = tid + r * 128;
        int row = idx >> 4, c4 = (idx & 15) * 4;
        pF[r] = *(const float4*)(Ff + (size_t)(tbase + row) * 64 + c4);
    }
#pragma unroll
    for (int r = 0; r < 4; r++) {
        int idx = tid + r * 128;
        int row = idx >> 5, c4 = (idx & 31) * 4;
        float4 w = make_float4(fmaf(sgn, v[r].x, u[r].x), fmaf(sgn, v[r].y, u[r].y),
                               fmaf(sgn, v[r].z, u[r].z), fmaf(sgn, v[r].w, u[r].w));
        *(float4*)&As[0][row * 128 + c4] = w;
    }
#pragma unroll
    for (int r = 0; r < 2; r++) {
        int idx = tid + r * 128;
        int row = idx >> 4, c4 = (idx & 15) * 4;
        *(float4*)&Bs[0][row * 64 + c4] = pF[r];
    }
    __syncthreads();

    const int NCH = 32;   // 512 / 16
    for (int it = 0; it < NCH; it++) {
        int p = it & 1;
        if (it + 1 < NCH) {
            int t0 = tbase + (it + 1) * 16;
#pragma unroll
            for (int r = 0; r < 4; r++) {
                int idx = tid + r * 128;
                int row = idx >> 5, c4 = (idx & 31) * 4;
                u[r] = *(const float4*)(x + (size_t)(t0 + row) * 512 + c4);
                v[r] = *(const float4*)(x + (size_t)(t0 + row + 1024) * 512 + c4);
            }
#pragma unroll
            for (int r = 0; r < 2; r++) {
                int idx = tid + r * 128;
                int row = idx >> 4, c4 = (idx & 15) * 4;
                pF[r] = *(const float4*)(Ff + (size_t)(t0 + row) * 64 + c4);
            }
        }
#pragma unroll
        for (int tk = 0; tk < 16; tk++) {
            float4 a0 = *(float4*)&As[p][tk * 128 + r0];
            float4 a1 = *(float4*)&As[p][tk * 128 + r0 + 4];
            ull bv[4];
#pragma unroll
            for (int j = 0; j < 4; j++) bv[j] = *(ull*)&Bs[p][tk * 64 + j * 16 + 2 * tx];
            ull ad[8] = {dup2(a0.x), dup2(a0.y), dup2(a0.z), dup2(a0.w),
                         dup2(a1.x), dup2(a1.y), dup2(a1.z), dup2(a1.w)};
#pragma unroll
            for (int i = 0; i < 8; i++)
#pragma unroll
                for (int j = 0; j < 4; j++) fma2(acc[i][j], ad[i], bv[j]);
        }
        if (it + 1 < NCH) {
            int np = (it + 1) & 1;
#pragma unroll
            for (int r = 0; r < 4; r++) {
                int idx = tid + r * 128;
                int row = idx >> 5, c4 = (idx & 31) * 4;
                float4 w = make_float4(fmaf(sgn, v[r].x, u[r].x), fmaf(sgn, v[r].y, u[r].y),
                                       fmaf(sgn, v[r].z, u[r].z), fmaf(sgn, v[r].w, u[r].w));
                *(float4*)&As[np][row * 128 + c4] = w;
            }
#pragma unroll
            for (int r = 0; r < 2; r++) {
                int idx = tid + r * 128;
                int row = idx >> 4, c4 = (idx & 15) * 4;
                *(float4*)&Bs[np][row * 64 + c4] = pF[r];
            }
            __syncthreads();
        }
    }

    int bh0 = b * 8 + h0;
    const int* cm = g_cmap[src][par];
#pragma unroll
    for (int j = 0; j < 4; j++) {
        int c = j * 16 + 2 * tx;
        int m0 = cm[c], m1 = cm[c + 1];
#pragma unroll
        for (int i = 0; i < 8; i++) {
            int row = r0 + i;
            int e = row & 63;
            int bh = bh0 + (row >> 6);
            float* G = g_G[ks][src][bh];
            float2 vv = unpk(acc[i][j]);
            G[e * 64 + m0] = vv.x;
            G[e * 64 + m1] = vv.y;
        }
    }
}

// ---------------- K2a: projections X = W*G + bias ----------------
__global__ void __launch_bounds__(256) k_proj(
    const float* __restrict__ wq_w, const float* __restrict__ wq_b,
    const float* __restrict__ wk_w, const float* __restrict__ wk_b,
    const int* __restrict__ idxq,   const int* __restrict__ idxkv) {
    extern __shared__ float sm[];
    float* sG = sm;          // 8192
    float* sW = sm + 8192;   // 4096

    int bx = blockIdx.x;
    int src = bx >> 7;
    int bh  = bx & 127;
    const float* Wm   = src ? wk_w : wq_w;
    const float* bias = src ? wk_b : wq_b;
    const int*   idx  = src ? idxkv : idxq;
    int tid = threadIdx.x;

#pragma unroll
    for (int r = 0; r < 8; r++) {
        float4 a = ((const float4*)(g_G[0][src][bh]))[r * 256 + tid];
        float4 a1 = ((const float4*)(g_G[1][src][bh]))[r * 256 + tid];
        a.x += a1.x; a.y += a1.y; a.z += a1.z; a.w += a1.w;
        ((float4*)sG)[r * 256 + tid] = a;
    }
#pragma unroll
    for (int r = 0; r < 4; r++)
        ((float4*)sW)[r * 256 + tid] = ((const float4*)Wm)[r * 256 + tid];
    __syncthreads();

    float* Xout = g_X[src][bh];
#pragma unroll 1
    for (int kk = 0; kk < 8; kk++) {
        int pidx = kk * 256 + tid;
        int ep = pidx >> 5, mp = pidx & 31;
        ull ar0 = 0ULL, ar1 = 0ULL, ai0 = 0ULL, ai1 = 0ULL;
#pragma unroll 8
        for (int e = 0; e < 32; e++) {
            ull wd0 = dup2(sW[ep * 64 + e]);
            ull wd1 = dup2(sW[ep * 64 + 32 + e]);
            fma2(ar0, wd0, *(ull*)&sG[e * 64 + mp * 2]);
            fma2(ar1, wd1, *(ull*)&sG[(32 + e) * 64 + mp * 2]);
            fma2(ai0, wd0, *(ull*)&sG[4096 + e * 64 + mp * 2]);
            fma2(ai1, wd1, *(ull*)&sG[4096 + (32 + e) * 64 + mp * 2]);
        }
        float2 arf = unpk(add2(ar0, ar1)), aif = unpk(add2(ai0, ai1));
        float bb = 2048.f * bias[ep];
        if (idx[2 * mp] == 0)     arf.x += bb;
        if (idx[2 * mp + 1] == 0) arf.y += bb;
        *(float2*)&Xout[ep * 64 + mp * 2] = arf;
        *(float2*)&Xout[4096 + ep * 64 + mp * 2] = aif;
    }
}

// ---------------- K2b: scores + tanh + apply -> Z (per 16-x slice) ----------------
__global__ void __launch_bounds__(256) k_attn(const int* __restrict__ idxq) {
    extern __shared__ float sm[];
    float* sXq = sm;            // 2048: [p][e][x16]
    float* sXk = sm + 2048;     // 8192: [p][e][y64]
    float* sS  = sm + 10240;    // 2048: [p][y][x16]

    int bx = blockIdx.x;
    int bh = bx >> 2;
    int xc = bx & 3;
    int x0 = xc * 16;
    int tid = threadIdx.x;

    const float* Xq = g_X[0][bh];
#pragma unroll
    for (int r = 0; r < 2; r++) {
        int idx = r * 256 + tid;
        int p = idx >> 8, rem = idx & 255;
        int e = rem >> 2, c = rem & 3;
        ((float4*)sXq)[idx] = *(const float4*)(Xq + p * 4096 + e * 64 + x0 + c * 4);
    }
    const float4* Xk4 = (const float4*)(g_X[1][bh]);
#pragma unroll
    for (int r = 0; r < 8; r++)
        ((float4*)sXk)[r * 256 + tid] = Xk4[r * 256 + tid];
    __syncthreads();

#pragma unroll 1
    for (int kk = 0; kk < 2; kk++) {
        int pidx = kk * 256 + tid;
        int y = pidx >> 3, xp = pidx & 7;
        ull sr0 = 0ULL, sr1 = 0ULL, si0 = 0ULL, si1 = 0ULL;
#pragma unroll 8
        for (int e = 0; e < 32; e++) {
            ull qr0 = *(ull*)&sXq[e * 16 + xp * 2];
            ull qi0 = *(ull*)&sXq[1024 + e * 16 + xp * 2];
            ull qr1 = *(ull*)&sXq[(32 + e) * 16 + xp * 2];
            ull qi1 = *(ull*)&sXq[1024 + (32 + e) * 16 + xp * 2];
            float kr0 = sXk[e * 64 + y],        ki0 = sXk[4096 + e * 64 + y];
            float kr1 = sXk[(32 + e) * 64 + y], ki1 = sXk[4096 + (32 + e) * 64 + y];
            fma2(sr0, qr0, dup2(kr0)); fma2(sr0, qi0, dup2(-ki0));
            fma2(si0, qr0, dup2(ki0)); fma2(si0, qi0, dup2(kr0));
            fma2(sr1, qr1, dup2(kr1)); fma2(sr1, qi1, dup2(-ki1));
            fma2(si1, qr1, dup2(ki1)); fma2(si1, qi1, dup2(kr1));
        }
        float2 srf = unpk(add2(sr0, sr1)), sif = unpk(add2(si0, si1));
        srf.x = tanhf(srf.x); srf.y = tanhf(srf.y);
        sif.x = tanhf(sif.x); sif.y = tanhf(sif.y);
        *(float2*)&sS[y * 16 + xp * 2] = srf;
        *(float2*)&sS[1024 + y * 16 + xp * 2] = sif;
    }
    __syncthreads();

    float* Zout = g_Z[bh];
#pragma unroll 1
    for (int kk = 0; kk < 2; kk++) {
        int pidx = kk * 256 + tid;
        int e = pidx >> 3, xp = pidx & 7;
        ull zr0 = 0ULL, zr1 = 0ULL, zi0 = 0ULL, zi1 = 0ULL;
#pragma unroll 8
        for (int y = 0; y < 32; y++) {
            ull s_r0 = *(ull*)&sS[y * 16 + xp * 2];
            ull s_i0 = *(ull*)&sS[1024 + y * 16 + xp * 2];
            ull s_r1 = *(ull*)&sS[(32 + y) * 16 + xp * 2];
            ull s_i1 = *(ull*)&sS[1024 + (32 + y) * 16 + xp * 2];
            float kr0 = sXk[e * 64 + y],      ki0 = sXk[4096 + e * 64 + y];
            float kr1 = sXk[e * 64 + 32 + y], ki1 = sXk[4096 + e * 64 + 32 + y];
            fma2(zr0, s_r0, dup2(kr0)); fma2(zr0, s_i0, dup2(-ki0));
            fma2(zi0, s_r0, dup2(ki0)); fma2(zi0, s_i0, dup2(kr0));
            fma2(zr1, s_r1, dup2(kr1)); fma2(zr1, s_i1, dup2(-ki1));
            fma2(zi1, s_r1, dup2(ki1)); fma2(zi1, s_i1, dup2(kr1));
        }
        float2 zrf = unpk(add2(zr0, zr1)), zif = unpk(add2(zi0, zi1));
        *(float2*)&Zout[e * 64 + x0 + xp * 2]        = zrf;
        *(float2*)&Zout[4096 + e * 64 + x0 + xp * 2] = zif;
    }
}

// ---------------- K2c: apply complex weights, batched over b; parity-grouped Y ----------------
__global__ void __launch_bounds__(256) k_apply(
    const float* __restrict__ W1, const float* __restrict__ W2,
    const int* __restrict__ idxq) {
    extern __shared__ ull smu[];
    ull* sWr = smu;          // 4096 ull
    ull* sWi = smu + 4096;
    ull* sZ  = smu + 8192;   // 2048 ull

    int bx = blockIdx.x;
    int h   = bx >> 5;
    int xp2 = bx & 31;
    int x0  = xp2 * 2;
    int tid = threadIdx.x;

    const float* W1h = W1 + (size_t)h * 262144 + x0;
    const float* W2h = W2 + (size_t)h * 262144 + x0;
#pragma unroll
    for (int r = 0; r < 16; r++) {
        int idx = r * 256 + tid;
        sWr[idx] = *(const ull*)(W1h + (size_t)idx * 64);
        sWi[idx] = *(const ull*)(W2h + (size_t)idx * 64);
    }
#pragma unroll
    for (int r = 0; r < 8; r++) {
        int idx = r * 256 + tid;
        int b = idx >> 7, rem = idx & 127;
        sZ[idx] = *(const ull*)(g_Z[b * 8 + h] + (rem >> 6) * 4096 + (rem & 63) * 64 + x0);
    }
    __syncthreads();

    int o  = tid & 63;
    int bq = tid >> 6;

    ull yr[4], yi[4];
#pragma unroll
    for (int j = 0; j < 4; j++) { yr[j] = 0ULL; yi[j] = 0ULL; }

#pragma unroll 4
    for (int e = 0; e < 64; e++) {
        ull wr = sWr[e * 64 + o];
        ull wi = sWi[e * 64 + o];
#pragma unroll
        for (int j = 0; j < 4; j++) {
            int b = bq + j * 4;
            ull zr = sZ[b * 128 + e];
            ull zi = sZ[b * 128 + 64 + e];
            fma2(yr[j], zr, wr); fma2(yr[j], neg2(zi), wi);
            fma2(yi[j], zr, wi); fma2(yi[j], zi, wr);
        }
    }

    const float SC = 1.862645149230957e-9f;  // 2^-29
    int f0 = idxq[x0], f1 = idxq[x0 + 1];
    bool dc0 = (f0 == 0) | (f0 == 1024);
    bool dc1 = (f1 == 0) | (f1 == 1024);
    float ca0 = dc0 ? SC : 2.f * SC;
    float ca1 = dc1 ? SC : 2.f * SC;
    float cb0 = dc0 ? 0.f : -2.f * SC;
    float cb1 = dc1 ? 0.f : -2.f * SC;
    int s0 = g_pmap[x0], s1 = g_pmap[x0 + 1];

#pragma unroll
    for (int j = 0; j < 4; j++) {
        int b = bq + j * 4;
        float* Yout = g_Y + (size_t)(b * 8 + h) * 8192;
        float2 r = unpk(yr[j]), im = unpk(yi[j]);
        Yout[s0 * 64 + o]       = r.x * ca0;
        Yout[(s0 + 1) * 64 + o] = im.x * cb0;
        Yout[s1 * 64 + o]       = r.y * ca1;
        Yout[(s1 + 1) * 64 + o] = im.y * cb1;
    }
}

// ---------------- K3: folded inverse DFT GEMM ----------------
// grid (8, 128). 256 thr. K=128 (64 even-par + 64 odd-par). Outputs t and t+1024.
__global__ void __launch_bounds__(256) k_inv2(float* __restrict__ out) {
    __shared__ float As[2][16 * 64];
    __shared__ float Bs[2][16 * 128];

    int bh = blockIdx.y;
    int t0 = blockIdx.x * 128;   // within t<1024
    int tid = threadIdx.x;
    int ty = tid >> 4, tx = tid & 15;
    int o0 = ty * 4;
    const float* Yb = g_Y + (size_t)bh * 8192;

    int rA = tid >> 4, cA = (tid & 15) * 4;   // A: 1 float4/thread

    ull acc[2][4][4];
#pragma unroll
    for (int p = 0; p < 2; p++)
#pragma unroll
        for (int i = 0; i < 4; i++)
#pragma unroll
            for (int j = 0; j < 4; j++) acc[p][i][j] = 0ULL;

    float4 pA, pB[2];
    pA = *(const float4*)(Yb + (size_t)rA * 64 + cA);
#pragma unroll
    for (int r = 0; r < 2; r++) {
        int idx = tid + r * 256;
        int row = idx >> 5, col = (idx & 31) * 4;
        pB[r] = *(const float4*)(g_Binv2 + (size_t)row * 1024 + t0 + col);
    }
    *(float4*)&As[0][rA * 64 + cA] = pA;
#pragma unroll
    for (int r = 0; r < 2; r++) {
        int idx = tid + r * 256;
        int row = idx >> 5, col = (idx & 31) * 4;
        *(float4*)&Bs[0][row * 128 + col] = pB[r];
    }
    __syncthreads();

    for (int kt = 0; kt < 8; kt++) {
        int p = kt & 1;
        if (kt + 1 < 8) {
            int k0 = (kt + 1) * 16;
            pA = *(const float4*)(Yb + (size_t)(k0 + rA) * 64 + cA);
#pragma unroll
            for (int r = 0; r < 2; r++) {
                int idx = tid + r * 256;
                int row = idx >> 5, col = (idx & 31) * 4;
                pB[r] = *(const float4*)(g_Binv2 + (size_t)(k0 + row) * 1024 + t0 + col);
            }
        }
        int pg = kt >> 2;   // 0: even slots, 1: odd slots
#pragma unroll
        for (int tk = 0; tk < 16; tk++) {
            float4 a = *(float4*)&As[p][tk * 64 + o0];
            ull bv[4];
#pragma unroll
            for (int j = 0; j < 4; j++) bv[j] = *(ull*)&Bs[p][tk * 128 + j * 32 + tx * 2];
            ull ad[4] = {dup2(a.x), dup2(a.y), dup2(a.z), dup2(a.w)};
#pragma unroll
            for (int i = 0; i < 4; i++)
#pragma unroll
                for (int j = 0; j < 4; j++) fma2(acc[pg][i][j], ad[i], bv[j]);
        }
        if (kt + 1 < 8) {
            int np = (kt + 1) & 1;
            *(float4*)&As[np][rA * 64 + cA] = pA;
#pragma unroll
            for (int r = 0; r < 2; r++) {
                int idx = tid + r * 256;
                int row = idx >> 5, col = (idx & 31) * 4;
                *(float4*)&Bs[np][row * 128 + col] = pB[r];
            }
            __syncthreads();
        }
    }

    float* op = out + (size_t)bh * 64 * LSEQ;
#pragma unroll
    for (int i = 0; i < 4; i++) {
        int o = o0 + i;
#pragma unroll
        for (int j = 0; j < 4; j++) {
            int tsub = j * 32 + tx * 2;
            ull E = acc[0][i][j], O = acc[1][i][j];
            *(ull*)(op + (size_t)o * LSEQ + t0 + tsub)        = add2(E, O);
            *(ull*)(op + (size_t)o * LSEQ + 1024 + t0 + tsub) = add2(E, neg2(O));
        }
    }
}

// ---------------- launch ----------------
extern "C" void kernel_launch(void* const* d_in, const int* in_sizes, int n_in,
                              void* d_out, int out_size) {
    const float* q    = (const float*)d_in[0];
    const float* k    = (const float*)d_in[1];
    const float* wq_w = (const float*)d_in[3];
    const float* wq_b = (const float*)d_in[4];
    const float* wk_w = (const float*)d_in[5];
    const float* wk_b = (const float*)d_in[6];
    const float* W1   = (const float*)d_in[9];
    const float* W2   = (const float*)d_in[10];
    const int*  idxq  = (const int*)d_in[11];
    const int*  idxkv = (const int*)d_in[12];
    float* out = (float*)d_out;

    cudaFuncSetAttribute(k_proj,  cudaFuncAttributeMaxDynamicSharedMemorySize, 49152);
    cudaFuncSetAttribute(k_attn,  cudaFuncAttributeMaxDynamicSharedMemorySize, 49152);
    cudaFuncSetAttribute(k_apply, cudaFuncAttributeMaxDynamicSharedMemorySize, 81920);

    k_init_binv2<<<(1024 * 64 + 255) / 256, 256>>>(idxq);
    k_init_f<<<(1024 * 64 + 255) / 256, 256>>>(idxq, 0);
    k_init_f<<<(1024 * 64 + 255) / 256, 256>>>(idxkv, 1);
    k_fwd3<<<512, 128>>>(q, k);
    k_proj<<<256, 256, 49152>>>(wq_w, wq_b, wk_w, wk_b, idxq, idxkv);
    k_attn<<<512, 256, 49152>>>(idxq);
    k_apply<<<256, 256, 81920>>>(W1, W2, idxq);
    k_inv2<<<dim3(8, 128), 256>>>(out);
}

// round 9
// speedup vs baseline: 1.7877x; 1.7877x over previous
#include <cuda_runtime.h>

#define LSEQ 2048
#define NBH 128
typedef unsigned long long ull;

// -------- device scratch --------
__device__ float g_F[2][2][1024 * 64];   // [src][par][t<1024][64 grouped cols]
__device__ int   g_cmap[2][2][64];       // grouped col -> pl*4096 + m
__device__ float g_Binv2[128 * 1024];    // [kslot][t<1024] parity-grouped cos/sin
__device__ int   g_pmap[64];             // mode m -> kslot (cos; sin at +1)
__device__ float g_G[2][2][NBH][8192];   // [ks][src][bh][pl][e][m]
__device__ float g_X[2][NBH][8192];      // projected spectra
__device__ float g_Z[NBH][8192];         // attention-applied spectra [bh][pl][e][x]
__device__ float g_Y[NBH * 8192];        // irDFT coeffs, parity-grouped [bh][kslot][o]

// -------- f32x2 helpers --------
__device__ __forceinline__ ull dup2(float x) {
    ull r; asm("mov.b64 %0, {%1, %1};" : "=l"(r) : "f"(x)); return r;
}
__device__ __forceinline__ void fma2(ull& d, ull a, ull b) {
    asm("fma.rn.f32x2 %0, %1, %2, %3;" : "=l"(d) : "l"(a), "l"(b), "l"(d));
}
__device__ __forceinline__ ull add2(ull a, ull b) {
    ull r; asm("add.rn.f32x2 %0, %1, %2;" : "=l"(r) : "l"(a), "l"(b)); return r;
}
__device__ __forceinline__ float2 unpk(ull v) {
    float2 r; asm("mov.b64 {%0, %1}, %2;" : "=f"(r.x), "=f"(r.y) : "l"(v)); return r;
}
__device__ __forceinline__ ull neg2(ull v) { return v ^ 0x8000000080000000ULL; }

// ---------------- init: all tables in one launch ----------------
__global__ void k_init_all(const int* __restrict__ idxq, const int* __restrict__ idxkv) {
    int gidx = blockIdx.x * blockDim.x + threadIdx.x;
    if (gidx >= 1024 * 64) return;
    int t = gidx >> 6, m = gidx & 63;

    // q side: forward basis + inverse basis + maps
    int fq = idxq[m];
    int pq = fq & 1;
    int rq = 0;
    for (int mm = 0; mm < m; mm++) rq += ((idxq[mm] & 1) == pq);
    float sn, cs;
    int r = (fq * t) & (LSEQ - 1);
    sincospif((float)r * (1.0f / 1024.0f), &sn, &cs);
    float* Fq = g_F[0][pq];
    Fq[t * 64 + 2 * rq]     = cs;
    Fq[t * 64 + 2 * rq + 1] = -sn;
    int slot = pq * 64 + 2 * rq;
    g_Binv2[slot * 1024 + t]       = cs;
    g_Binv2[(slot + 1) * 1024 + t] = sn;
    if (t == 0) {
        g_cmap[0][pq][2 * rq]     = m;
        g_cmap[0][pq][2 * rq + 1] = 4096 + m;
        g_pmap[m] = slot;
    }

    // k side: forward basis + map
    int fk = idxkv[m];
    int pk = fk & 1;
    int rk = 0;
    for (int mm = 0; mm < m; mm++) rk += ((idxkv[mm] & 1) == pk);
    int r2 = (fk * t) & (LSEQ - 1);
    sincospif((float)r2 * (1.0f / 1024.0f), &sn, &cs);
    float* Fk = g_F[1][pk];
    Fk[t * 64 + 2 * rk]     = cs;
    Fk[t * 64 + 2 * rk + 1] = -sn;
    if (t == 0) {
        g_cmap[1][pk][2 * rk]     = m;
        g_cmap[1][pk][2 * rk + 1] = 4096 + m;
    }
}

// ---------------- K1: folded forward DFT GEMM (R7-proven: 256 thr) ----------------
// grid 512: (par, ks, pair, src). C[128 rows(2 heads)][64 grouped cols], K=512.
__global__ void __launch_bounds__(256) k_fwd2(const float* __restrict__ q,
                                              const float* __restrict__ k) {
    int bx = blockIdx.x;
    int par  = bx & 1;
    int ks   = (bx >> 1) & 1;
    int pair = (bx >> 2) & 63;
    int src  = bx >> 8;
    int b  = pair >> 2;
    int h0 = (pair & 3) * 2;
    const float* x  = (src == 0 ? q : k) + (size_t)b * (LSEQ * 512) + h0 * 64;
    const float* Ff = g_F[src][par];
    const float sgn = par ? -1.f : 1.f;
    int tbase = ks * 512;

    __shared__ float As[2][16 * 128];
    __shared__ float Bs[2][16 * 64];

    int tid = threadIdx.x;
    int ty = tid >> 4, tx = tid & 15;
    int r0 = ty * 8;

    int i0 = tid, i1 = tid + 256;
    int rA0 = i0 >> 5, cA0 = (i0 & 31) * 4;
    int rA1 = i1 >> 5, cA1 = (i1 & 31) * 4;
    int rB = tid >> 4, cB = (tid & 15) * 4;

    ull acc[8][2];
#pragma unroll
    for (int i = 0; i < 8; i++) { acc[i][0] = 0ULL; acc[i][1] = 0ULL; }

    float4 u0, v0, u1, v1, pB;
    {
        int t0 = tbase;
        u0 = *(const float4*)(x + (size_t)(t0 + rA0) * 512 + cA0);
        v0 = *(const float4*)(x + (size_t)(t0 + rA0 + 1024) * 512 + cA0);
        u1 = *(const float4*)(x + (size_t)(t0 + rA1) * 512 + cA1);
        v1 = *(const float4*)(x + (size_t)(t0 + rA1 + 1024) * 512 + cA1);
        pB = *(const float4*)(Ff + (size_t)(t0 + rB) * 64 + cB);
    }
    {
        float4 w0 = make_float4(fmaf(sgn, v0.x, u0.x), fmaf(sgn, v0.y, u0.y),
                                fmaf(sgn, v0.z, u0.z), fmaf(sgn, v0.w, u0.w));
        float4 w1 = make_float4(fmaf(sgn, v1.x, u1.x), fmaf(sgn, v1.y, u1.y),
                                fmaf(sgn, v1.z, u1.z), fmaf(sgn, v1.w, u1.w));
        *(float4*)&As[0][rA0 * 128 + cA0] = w0;
        *(float4*)&As[0][rA1 * 128 + cA1] = w1;
        *(float4*)&Bs[0][rB * 64 + cB]    = pB;
    }
    __syncthreads();

    const int NCH = 32;   // 512 / 16
    for (int it = 0; it < NCH; it++) {
        int p = it & 1;
        if (it + 1 < NCH) {
            int t0 = tbase + (it + 1) * 16;
            u0 = *(const float4*)(x + (size_t)(t0 + rA0) * 512 + cA0);
            v0 = *(const float4*)(x + (size_t)(t0 + rA0 + 1024) * 512 + cA0);
            u1 = *(const float4*)(x + (size_t)(t0 + rA1) * 512 + cA1);
            v1 = *(const float4*)(x + (size_t)(t0 + rA1 + 1024) * 512 + cA1);
            pB = *(const float4*)(Ff + (size_t)(t0 + rB) * 64 + cB);
        }
#pragma unroll
        for (int tk = 0; tk < 16; tk++) {
            float4 a0 = *(float4*)&As[p][tk * 128 + r0];
            float4 a1 = *(float4*)&As[p][tk * 128 + r0 + 4];
            ull b0 = *(ull*)&Bs[p][tk * 64 + 2 * tx];
            ull b1 = *(ull*)&Bs[p][tk * 64 + 32 + 2 * tx];
            ull ad[8] = {dup2(a0.x), dup2(a0.y), dup2(a0.z), dup2(a0.w),
                         dup2(a1.x), dup2(a1.y), dup2(a1.z), dup2(a1.w)};
#pragma unroll
            for (int i = 0; i < 8; i++) {
                fma2(acc[i][0], ad[i], b0);
                fma2(acc[i][1], ad[i], b1);
            }
        }
        if (it + 1 < NCH) {
            int np = (it + 1) & 1;
            float4 w0 = make_float4(fmaf(sgn, v0.x, u0.x), fmaf(sgn, v0.y, u0.y),
                                    fmaf(sgn, v0.z, u0.z), fmaf(sgn, v0.w, u0.w));
            float4 w1 = make_float4(fmaf(sgn, v1.x, u1.x), fmaf(sgn, v1.y, u1.y),
                                    fmaf(sgn, v1.z, u1.z), fmaf(sgn, v1.w, u1.w));
            *(float4*)&As[np][rA0 * 128 + cA0] = w0;
            *(float4*)&As[np][rA1 * 128 + cA1] = w1;
            *(float4*)&Bs[np][rB * 64 + cB]    = pB;
            __syncthreads();
        }
    }

    int bh0 = b * 8 + h0;
    const int* cm = g_cmap[src][par];
#pragma unroll
    for (int j = 0; j < 2; j++) {
        int c = j * 32 + 2 * tx;
        int m0 = cm[c], m1 = cm[c + 1];
#pragma unroll
        for (int i = 0; i < 8; i++) {
            int row = r0 + i;
            int e = row & 63;
            int bh = bh0 + (row >> 6);
            float* G = g_G[ks][src][bh];
            float2 v = unpk(acc[i][j]);
            G[e * 64 + m0] = v.x;
            G[e * 64 + m1] = v.y;
        }
    }
}

// ---------------- K2a: projections X = W*G + bias ----------------
__global__ void __launch_bounds__(256) k_proj(
    const float* __restrict__ wq_w, const float* __restrict__ wq_b,
    const float* __restrict__ wk_w, const float* __restrict__ wk_b,
    const int* __restrict__ idxq,   const int* __restrict__ idxkv) {
    extern __shared__ float sm[];
    float* sG = sm;          // 8192
    float* sW = sm + 8192;   // 4096

    int bx = blockIdx.x;
    int src = bx >> 7;
    int bh  = bx & 127;
    const float* Wm   = src ? wk_w : wq_w;
    const float* bias = src ? wk_b : wq_b;
    const int*   idx  = src ? idxkv : idxq;
    int tid = threadIdx.x;

#pragma unroll
    for (int r = 0; r < 8; r++) {
        float4 a = ((const float4*)(g_G[0][src][bh]))[r * 256 + tid];
        float4 a1 = ((const float4*)(g_G[1][src][bh]))[r * 256 + tid];
        a.x += a1.x; a.y += a1.y; a.z += a1.z; a.w += a1.w;
        ((float4*)sG)[r * 256 + tid] = a;
    }
#pragma unroll
    for (int r = 0; r < 4; r++)
        ((float4*)sW)[r * 256 + tid] = ((const float4*)Wm)[r * 256 + tid];
    __syncthreads();

    float* Xout = g_X[src][bh];
#pragma unroll 1
    for (int kk = 0; kk < 8; kk++) {
        int pidx = kk * 256 + tid;
        int ep = pidx >> 5, mp = pidx & 31;
        ull ar0 = 0ULL, ar1 = 0ULL, ai0 = 0ULL, ai1 = 0ULL;
#pragma unroll 8
        for (int e = 0; e < 32; e++) {
            ull wd0 = dup2(sW[ep * 64 + e]);
            ull wd1 = dup2(sW[ep * 64 + 32 + e]);
            fma2(ar0, wd0, *(ull*)&sG[e * 64 + mp * 2]);
            fma2(ar1, wd1, *(ull*)&sG[(32 + e) * 64 + mp * 2]);
            fma2(ai0, wd0, *(ull*)&sG[4096 + e * 64 + mp * 2]);
            fma2(ai1, wd1, *(ull*)&sG[4096 + (32 + e) * 64 + mp * 2]);
        }
        float2 arf = unpk(add2(ar0, ar1)), aif = unpk(add2(ai0, ai1));
        float bb = 2048.f * bias[ep];
        if (idx[2 * mp] == 0)     arf.x += bb;
        if (idx[2 * mp + 1] == 0) arf.y += bb;
        *(float2*)&Xout[ep * 64 + mp * 2] = arf;
        *(float2*)&Xout[4096 + ep * 64 + mp * 2] = aif;
    }
}

// ---------------- K2b: scores + tanh + apply -> Z (per 16-x slice) ----------------
__global__ void __launch_bounds__(256) k_attn(const int* __restrict__ idxq) {
    extern __shared__ float sm[];
    float* sXq = sm;            // 2048: [p][e][x16]
    float* sXk = sm + 2048;     // 8192: [p][e][y64]
    float* sS  = sm + 10240;    // 2048: [p][y][x16]

    int bx = blockIdx.x;
    int bh = bx >> 2;
    int xc = bx & 3;
    int x0 = xc * 16;
    int tid = threadIdx.x;

    const float* Xq = g_X[0][bh];
#pragma unroll
    for (int r = 0; r < 2; r++) {
        int idx = r * 256 + tid;
        int p = idx >> 8, rem = idx & 255;
        int e = rem >> 2, c = rem & 3;
        ((float4*)sXq)[idx] = *(const float4*)(Xq + p * 4096 + e * 64 + x0 + c * 4);
    }
    const float4* Xk4 = (const float4*)(g_X[1][bh]);
#pragma unroll
    for (int r = 0; r < 8; r++)
        ((float4*)sXk)[r * 256 + tid] = Xk4[r * 256 + tid];
    __syncthreads();

#pragma unroll 1
    for (int kk = 0; kk < 2; kk++) {
        int pidx = kk * 256 + tid;
        int y = pidx >> 3, xp = pidx & 7;
        ull sr0 = 0ULL, sr1 = 0ULL, si0 = 0ULL, si1 = 0ULL;
#pragma unroll 8
        for (int e = 0; e < 32; e++) {
            ull qr0 = *(ull*)&sXq[e * 16 + xp * 2];
            ull qi0 = *(ull*)&sXq[1024 + e * 16 + xp * 2];
            ull qr1 = *(ull*)&sXq[(32 + e) * 16 + xp * 2];
            ull qi1 = *(ull*)&sXq[1024 + (32 + e) * 16 + xp * 2];
            float kr0 = sXk[e * 64 + y],        ki0 = sXk[4096 + e * 64 + y];
            float kr1 = sXk[(32 + e) * 64 + y], ki1 = sXk[4096 + (32 + e) * 64 + y];
            fma2(sr0, qr0, dup2(kr0)); fma2(sr0, qi0, dup2(-ki0));
            fma2(si0, qr0, dup2(ki0)); fma2(si0, qi0, dup2(kr0));
            fma2(sr1, qr1, dup2(kr1)); fma2(sr1, qi1, dup2(-ki1));
            fma2(si1, qr1, dup2(ki1)); fma2(si1, qi1, dup2(kr1));
        }
        float2 srf = unpk(add2(sr0, sr1)), sif = unpk(add2(si0, si1));
        srf.x = tanhf(srf.x); srf.y = tanhf(srf.y);
        sif.x = tanhf(sif.x); sif.y = tanhf(sif.y);
        *(float2*)&sS[y * 16 + xp * 2] = srf;
        *(float2*)&sS[1024 + y * 16 + xp * 2] = sif;
    }
    __syncthreads();

    float* Zout = g_Z[bh];
#pragma unroll 1
    for (int kk = 0; kk < 2; kk++) {
        int pidx = kk * 256 + tid;
        int e = pidx >> 3, xp = pidx & 7;
        ull zr0 = 0ULL, zr1 = 0ULL, zi0 = 0ULL, zi1 = 0ULL;
#pragma unroll 8
        for (int y = 0; y < 32; y++) {
            ull s_r0 = *(ull*)&sS[y * 16 + xp * 2];
            ull s_i0 = *(ull*)&sS[1024 + y * 16 + xp * 2];
            ull s_r1 = *(ull*)&sS[(32 + y) * 16 + xp * 2];
            ull s_i1 = *(ull*)&sS[1024 + (32 + y) * 16 + xp * 2];
            float kr0 = sXk[e * 64 + y],      ki0 = sXk[4096 + e * 64 + y];
            float kr1 = sXk[e * 64 + 32 + y], ki1 = sXk[4096 + e * 64 + 32 + y];
            fma2(zr0, s_r0, dup2(kr0)); fma2(zr0, s_i0, dup2(-ki0));
            fma2(zi0, s_r0, dup2(ki0)); fma2(zi0, s_i0, dup2(kr0));
            fma2(zr1, s_r1, dup2(kr1)); fma2(zr1, s_i1, dup2(-ki1));
            fma2(zi1, s_r1, dup2(ki1)); fma2(zi1, s_i1, dup2(kr1));
        }
        float2 zrf = unpk(add2(zr0, zr1)), zif = unpk(add2(zi0, zi1));
        *(float2*)&Zout[e * 64 + x0 + xp * 2]        = zrf;
        *(float2*)&Zout[4096 + e * 64 + x0 + xp * 2] = zif;
    }
}

// ---------------- K2c: apply complex weights, batched over b; parity-grouped Y ----------------
__global__ void __launch_bounds__(256) k_apply(
    const float* __restrict__ W1, const float* __restrict__ W2,
    const int* __restrict__ idxq) {
    extern __shared__ ull smu[];
    ull* sWr = smu;          // 4096 ull
    ull* sWi = smu + 4096;
    ull* sZ  = smu + 8192;   // 2048 ull

    int bx = blockIdx.x;
    int h   = bx >> 5;
    int xp2 = bx & 31;
    int x0  = xp2 * 2;
    int tid = threadIdx.x;

    const float* W1h = W1 + (size_t)h * 262144 + x0;
    const float* W2h = W2 + (size_t)h * 262144 + x0;
#pragma unroll
    for (int r = 0; r < 16; r++) {
        int idx = r * 256 + tid;
        sWr[idx] = *(const ull*)(W1h + (size_t)idx * 64);
        sWi[idx] = *(const ull*)(W2h + (size_t)idx * 64);
    }
#pragma unroll
    for (int r = 0; r < 8; r++) {
        int idx = r * 256 + tid;
        int b = idx >> 7, rem = idx & 127;
        sZ[idx] = *(const ull*)(g_Z[b * 8 + h] + (rem >> 6) * 4096 + (rem & 63) * 64 + x0);
    }
    __syncthreads();

    int o  = tid & 63;
    int bq = tid >> 6;

    ull yr[4], yi[4];
#pragma unroll
    for (int j = 0; j < 4; j++) { yr[j] = 0ULL; yi[j] = 0ULL; }

#pragma unroll 4
    for (int e = 0; e < 64; e++) {
        ull wr = sWr[e * 64 + o];
        ull wi = sWi[e * 64 + o];
#pragma unroll
        for (int j = 0; j < 4; j++) {
            int b = bq + j * 4;
            ull zr = sZ[b * 128 + e];
            ull zi = sZ[b * 128 + 64 + e];
            fma2(yr[j], zr, wr); fma2(yr[j], neg2(zi), wi);
            fma2(yi[j], zr, wi); fma2(yi[j], zi, wr);
        }
    }

    const float SC = 1.862645149230957e-9f;  // 2^-29
    int f0 = idxq[x0], f1 = idxq[x0 + 1];
    bool dc0 = (f0 == 0) | (f0 == 1024);
    bool dc1 = (f1 == 0) | (f1 == 1024);
    float ca0 = dc0 ? SC : 2.f * SC;
    float ca1 = dc1 ? SC : 2.f * SC;
    float cb0 = dc0 ? 0.f : -2.f * SC;
    float cb1 = dc1 ? 0.f : -2.f * SC;
    int s0 = g_pmap[x0], s1 = g_pmap[x0 + 1];

#pragma unroll
    for (int j = 0; j < 4; j++) {
        int b = bq + j * 4;
        float* Yout = g_Y + (size_t)(b * 8 + h) * 8192;
        float2 r = unpk(yr[j]), im = unpk(yi[j]);
        Yout[s0 * 64 + o]       = r.x * ca0;
        Yout[(s0 + 1) * 64 + o] = im.x * cb0;
        Yout[s1 * 64 + o]       = r.y * ca1;
        Yout[(s1 + 1) * 64 + o] = im.y * cb1;
    }
}

// ---------------- K3: folded inverse DFT GEMM (kt loop UNROLLED: static acc index) ----
// grid (8, 128). 256 thr. K=128 (64 even-par + 64 odd-par). Outputs t and t+1024.
__global__ void __launch_bounds__(256) k_inv2(float* __restrict__ out) {
    __shared__ float As[2][16 * 64];
    __shared__ float Bs[2][16 * 128];

    int bh = blockIdx.y;
    int t0 = blockIdx.x * 128;   // within t<1024
    int tid = threadIdx.x;
    int ty = tid >> 4, tx = tid & 15;
    int o0 = ty * 4;
    const float* Yb = g_Y + (size_t)bh * 8192;

    int rA = tid >> 4, cA = (tid & 15) * 4;   // A: 1 float4/thread

    ull acc[2][4][4];
#pragma unroll
    for (int p = 0; p < 2; p++)
#pragma unroll
        for (int i = 0; i < 4; i++)
#pragma unroll
            for (int j = 0; j < 4; j++) acc[p][i][j] = 0ULL;

    float4 pA, pB[2];
    pA = *(const float4*)(Yb + (size_t)rA * 64 + cA);
#pragma unroll
    for (int r = 0; r < 2; r++) {
        int idx = tid + r * 256;
        int row = idx >> 5, col = (idx & 31) * 4;
        pB[r] = *(const float4*)(g_Binv2 + (size_t)row * 1024 + t0 + col);
    }
    *(float4*)&As[0][rA * 64 + cA] = pA;
#pragma unroll
    for (int r = 0; r < 2; r++) {
        int idx = tid + r * 256;
        int row = idx >> 5, col = (idx & 31) * 4;
        *(float4*)&Bs[0][row * 128 + col] = pB[r];
    }
    __syncthreads();

#pragma unroll
    for (int kt = 0; kt < 8; kt++) {
        int p = kt & 1;
        if (kt + 1 < 8) {
            int k0 = (kt + 1) * 16;
            pA = *(const float4*)(Yb + (size_t)(k0 + rA) * 64 + cA);
#pragma unroll
            for (int r = 0; r < 2; r++) {
                int idx = tid + r * 256;
                int row = idx >> 5, col = (idx & 31) * 4;
                pB[r] = *(const float4*)(g_Binv2 + (size_t)(k0 + row) * 1024 + t0 + col);
            }
        }
        const int pg = kt >> 2;   // compile-time after unroll: 0 even, 1 odd
#pragma unroll
        for (int tk = 0; tk < 16; tk++) {
            float4 a = *(float4*)&As[p][tk * 64 + o0];
            ull bv[4];
#pragma unroll
            for (int j = 0; j < 4; j++) bv[j] = *(ull*)&Bs[p][tk * 128 + j * 32 + tx * 2];
            ull ad[4] = {dup2(a.x), dup2(a.y), dup2(a.z), dup2(a.w)};
#pragma unroll
            for (int i = 0; i < 4; i++)
#pragma unroll
                for (int j = 0; j < 4; j++) fma2(acc[pg][i][j], ad[i], bv[j]);
        }
        if (kt + 1 < 8) {
            int np = (kt + 1) & 1;
            *(float4*)&As[np][rA * 64 + cA] = pA;
#pragma unroll
            for (int r = 0; r < 2; r++) {
                int idx = tid + r * 256;
                int row = idx >> 5, col = (idx & 31) * 4;
                *(float4*)&Bs[np][row * 128 + col] = pB[r];
            }
            __syncthreads();
        }
    }

    float* op = out + (size_t)bh * 64 * LSEQ;
#pragma unroll
    for (int i = 0; i < 4; i++) {
        int o = o0 + i;
#pragma unroll
        for (int j = 0; j < 4; j++) {
            int tsub = j * 32 + tx * 2;
            ull E = acc[0][i][j], O = acc[1][i][j];
            *(ull*)(op + (size_t)o * LSEQ + t0 + tsub)        = add2(E, O);
            *(ull*)(op + (size_t)o * LSEQ + 1024 + t0 + tsub) = add2(E, neg2(O));
        }
    }
}

// ---------------- launch ----------------
extern "C" void kernel_launch(void* const* d_in, const int* in_sizes, int n_in,
                              void* d_out, int out_size) {
    const float* q    = (const float*)d_in[0];
    const float* k    = (const float*)d_in[1];
    const float* wq_w = (const float*)d_in[3];
    const float* wq_b = (const float*)d_in[4];
    const float* wk_w = (const float*)d_in[5];
    const float* wk_b = (const float*)d_in[6];
    const float* W1   = (const float*)d_in[9];
    const float* W2   = (const float*)d_in[10];
    const int*  idxq  = (const int*)d_in[11];
    const int*  idxkv = (const int*)d_in[12];
    float* out = (float*)d_out;

    cudaFuncSetAttribute(k_proj,  cudaFuncAttributeMaxDynamicSharedMemorySize, 49152);
    cudaFuncSetAttribute(k_attn,  cudaFuncAttributeMaxDynamicSharedMemorySize, 49152);
    cudaFuncSetAttribute(k_apply, cudaFuncAttributeMaxDynamicSharedMemorySize, 81920);

    k_init_all<<<(1024 * 64 + 255) / 256, 256>>>(idxq, idxkv);
    k_fwd2<<<512, 256>>>(q, k);
    k_proj<<<256, 256, 49152>>>(wq_w, wq_b, wk_w, wk_b, idxq, idxkv);
    k_attn<<<512, 256, 49152>>>(idxq);
    k_apply<<<256, 256, 81920>>>(W1, W2, idxq);
    k_inv2<<<dim3(8, 128), 256>>>(out);
}